// round 3
// baseline (speedup 1.0000x reference)
#include <cuda_runtime.h>
#include <stdint.h>

#define LOG2_HASHMAP_SIZE 19
#define HASHTABLE_SIZE (1u << LOG2_HASHMAP_SIZE)
#define HASH_MASK (HASHTABLE_SIZE - 1u)
#define RES 128.0f
#define P1 2654435761u
#define P2 805459861u

// Predicated 8-byte gather: no branch, predicated-off lanes produce no
// L1 wavefront and no L2 sector traffic.
__device__ __forceinline__ float2 ldg_cond(const float2* p, uint32_t do_load) {
    float2 v;
    asm("{\n\t"
        ".reg .pred %%pp;\n\t"
        "setp.ne.u32 %%pp, %2, 0;\n\t"
        "mov.f32 %0, 0f00000000;\n\t"
        "mov.f32 %1, 0f00000000;\n\t"
        "@%%pp ld.global.nc.v2.f32 {%0, %1}, [%3];\n\t"
        "}"
        : "=f"(v.x), "=f"(v.y)
        : "r"(do_load), "l"(p));
    return v;
}

__global__ void __launch_bounds__(256) ngp_interp_kernel(
    const float* __restrict__ x,
    const float2* __restrict__ ht,
    float2* __restrict__ out,
    int n)
{
    int i = blockIdx.x * blockDim.x + threadIdx.x;
    if (i >= n) return;

    // Streaming (evict-first) reads: don't displace the L2-resident table.
    float px = __ldcs(&x[3 * i + 0]);
    float py = __ldcs(&x[3 * i + 1]);
    float pz = __ldcs(&x[3 * i + 2]);

    float sx = px * RES;
    float sy = py * RES;
    float sz = pz * RES;

    float fxf = floorf(sx), fyf = floorf(sy), fzf = floorf(sz);
    uint32_t ufx = (uint32_t)(int)fxf;
    uint32_t ufy = (uint32_t)(int)fyf;
    uint32_t ufz = (uint32_t)(int)fzf;
    uint32_t ucx = (uint32_t)(int)ceilf(sx);
    uint32_t ucy = (uint32_t)(int)ceilf(sy);
    uint32_t ucz = (uint32_t)(int)ceilf(sz);

    float dx = sx - fxf;
    float dy = sy - fyf;
    float dz = sz - fzf;

    // y/z mix terms shared across the 4 x-pairs
    uint32_t yfP = ufy * P1, ycP = ucy * P1;
    uint32_t zfP = ufz * P2, zcP = ucz * P2;
    uint32_t mff = yfP ^ zfP;
    uint32_t mcf = ycP ^ zfP;
    uint32_t mfc = yfP ^ zcP;
    uint32_t mcc = ycP ^ zcP;

    uint32_t h000 = (ufx ^ mff) & HASH_MASK;
    uint32_t h010 = (ufx ^ mcf) & HASH_MASK;
    uint32_t h001 = (ufx ^ mfc) & HASH_MASK;
    uint32_t h011 = (ufx ^ mcc) & HASH_MASK;

    uint32_t dxor = ufx ^ ucx;          // h1xx = h0xx ^ dxor (XOR-linear in ix)
    uint32_t need = (dxor == 1u) ? 0u : 1u;

    const float4* __restrict__ ht4 = (const float4*)ht;

    // 4 unconditional 16B pair loads (each covers h0 and h0^1) — full MLP.
    float4 q00 = __ldg(&ht4[h000 >> 1]);
    float4 q10 = __ldg(&ht4[h010 >> 1]);
    float4 q01 = __ldg(&ht4[h001 >> 1]);
    float4 q11 = __ldg(&ht4[h011 >> 1]);

    // 4 predicated 8B loads for the non-mergeable lanes.
    uint32_t h100 = (ucx ^ mff) & HASH_MASK;
    uint32_t h110 = (ucx ^ mcf) & HASH_MASK;
    uint32_t h101 = (ucx ^ mfc) & HASH_MASK;
    uint32_t h111 = (ucx ^ mcc) & HASH_MASK;
    float2 l100 = ldg_cond(&ht[h100], need);
    float2 l110 = ldg_cond(&ht[h110], need);
    float2 l101 = ldg_cond(&ht[h101], need);
    float2 l111 = ldg_cond(&ht[h111], need);

    bool o00 = (h000 & 1u) != 0u;
    bool o10 = (h010 & 1u) != 0u;
    bool o01 = (h001 & 1u) != 0u;
    bool o11 = (h011 & 1u) != 0u;

    float2 v000 = o00 ? make_float2(q00.z, q00.w) : make_float2(q00.x, q00.y);
    float2 a000 = o00 ? make_float2(q00.x, q00.y) : make_float2(q00.z, q00.w);
    float2 v010 = o10 ? make_float2(q10.z, q10.w) : make_float2(q10.x, q10.y);
    float2 a010 = o10 ? make_float2(q10.x, q10.y) : make_float2(q10.z, q10.w);
    float2 v001 = o01 ? make_float2(q01.z, q01.w) : make_float2(q01.x, q01.y);
    float2 a001 = o01 ? make_float2(q01.x, q01.y) : make_float2(q01.z, q01.w);
    float2 v011 = o11 ? make_float2(q11.z, q11.w) : make_float2(q11.x, q11.y);
    float2 a011 = o11 ? make_float2(q11.x, q11.y) : make_float2(q11.z, q11.w);

    bool merge = (need == 0u);
    float2 v100 = merge ? a000 : l100;
    float2 v110 = merge ? a010 : l110;
    float2 v101 = merge ? a001 : l101;
    float2 v111 = merge ? a011 : l111;

    float omx = 1.0f - dx;
    float omy = 1.0f - dy;
    float omz = 1.0f - dz;

    // Match reference lerp order exactly.
    float c00a = v000.x * omx + v100.x * dx;
    float c00b = v000.y * omx + v100.y * dx;
    float c01a = v001.x * omx + v101.x * dx;
    float c01b = v001.y * omx + v101.y * dx;
    float c10a = v010.x * omx + v110.x * dx;
    float c10b = v010.y * omx + v110.y * dx;
    float c11a = v011.x * omx + v111.x * dx;
    float c11b = v011.y * omx + v111.y * dx;

    float c0a = c00a * omy + c10a * dy;
    float c0b = c00b * omy + c10b * dy;
    float c1a = c01a * omy + c11a * dy;
    float c1b = c01b * omy + c11b * dy;

    float oa = c0a * omz + c1a * dz;
    float ob = c0b * omz + c1b * dz;

    // Streaming store: evict-first, don't pollute L2.
    __stcs(&out[i], make_float2(oa, ob));
}

extern "C" void kernel_launch(void* const* d_in, const int* in_sizes, int n_in,
                              void* d_out, int out_size) {
    const float* x = (const float*)d_in[0];
    const float2* ht = (const float2*)d_in[1];
    float2* out = (float2*)d_out;
    int n = in_sizes[0] / 3;

    int threads = 256;
    int blocks = (n + threads - 1) / threads;
    ngp_interp_kernel<<<blocks, threads>>>(x, ht, out, n);
}